// round 1
// baseline (speedup 1.0000x reference)
#include <cuda_runtime.h>
#include <cuda_bf16.h>
#include <cstdint>

// Problem constants (fixed by the reference)
#define NN   50000
#define EE   800000
#define INC  128
#define OUTC 64
#define HH   4
#define HC   (HH*OUTC)   // 256
#define NEG  0.2f

// -------- scratch (device globals; no allocation allowed) --------
__device__ __align__(16) float    g_xh[(size_t)NN * HC];     // projected features [N,H,C]
__device__ __align__(16) float    g_accum[(size_t)NN * HC];  // unnormalized per-head aggregation
__device__ __align__(16) float    g_asrc[NN * HH];
__device__ __align__(16) float    g_adst[NN * HH];
__device__ __align__(16) unsigned g_amax[NN * HH];           // encoded float max
__device__ __align__(16) float    g_denom[NN * HH];

// float <-> order-preserving unsigned encoding (for atomicMax on floats)
__device__ __forceinline__ unsigned enc_f(float f) {
    unsigned u = __float_as_uint(f);
    return (u & 0x80000000u) ? ~u : (u | 0x80000000u);
}
__device__ __forceinline__ float dec_f(unsigned u) {
    u = (u & 0x80000000u) ? (u & 0x7FFFFFFFu) : ~u;
    return __uint_as_float(u);
}

__device__ __forceinline__ float leaky(float a) {
    return a > 0.f ? a : NEG * a;
}

// -------- K0: init scratch --------
__global__ void init_kernel() {
    int stride = gridDim.x * blockDim.x;
    for (size_t i = blockIdx.x * blockDim.x + threadIdx.x; i < (size_t)NN * HC; i += stride)
        g_accum[i] = 0.f;
    for (int i = blockIdx.x * blockDim.x + threadIdx.x; i < NN * HH; i += stride) {
        g_denom[i] = 0.f;
        g_amax[i]  = 0u;   // encodes "smaller than any real float"
    }
}

// -------- K1: SGEMM  xh = x[M,128] @ W[128,256] --------
#define BM 64
#define BN 64
#define BK 16
__global__ __launch_bounds__(256) void gemm_kernel(
    const float* __restrict__ A, const float* __restrict__ B)
{
    __shared__ float As[BK][BM];
    __shared__ float Bs[BK][BN];

    const int brow = blockIdx.y;      // 782 row blocks
    const int bcol = blockIdx.x;      // 4 col blocks of 64
    const int tid  = threadIdx.x;
    const int tcol = tid & 15;        // 0..15  (x)
    const int trow = tid >> 4;        // 0..15  (y)

    // A-tile load mapping: one float4 per thread, 64 rows x 4 float4
    const int rowA  = tid >> 2;       // 0..63
    const int colA4 = tid & 3;        // 0..3
    // B-tile load mapping: 16 rows x 16 float4
    const int rowB  = tid >> 4;       // 0..15
    const int colB4 = tid & 15;       // 0..15

    float acc[4][4];
    #pragma unroll
    for (int i = 0; i < 4; i++)
        #pragma unroll
        for (int j = 0; j < 4; j++) acc[i][j] = 0.f;

    const int grA = brow * BM + rowA;

    for (int k0 = 0; k0 < INC; k0 += BK) {
        float4 av = make_float4(0.f, 0.f, 0.f, 0.f);
        if (grA < NN)
            av = *reinterpret_cast<const float4*>(A + (size_t)grA * INC + k0 + colA4 * 4);
        As[colA4 * 4 + 0][rowA] = av.x;
        As[colA4 * 4 + 1][rowA] = av.y;
        As[colA4 * 4 + 2][rowA] = av.z;
        As[colA4 * 4 + 3][rowA] = av.w;

        float4 bv = *reinterpret_cast<const float4*>(
            B + (size_t)(k0 + rowB) * HC + bcol * BN + colB4 * 4);
        *reinterpret_cast<float4*>(&Bs[rowB][colB4 * 4]) = bv;

        __syncthreads();

        #pragma unroll
        for (int k = 0; k < BK; k++) {
            float4 rm = *reinterpret_cast<const float4*>(&As[k][trow * 4]);
            float4 rn = *reinterpret_cast<const float4*>(&Bs[k][tcol * 4]);
            float m[4] = {rm.x, rm.y, rm.z, rm.w};
            float n[4] = {rn.x, rn.y, rn.z, rn.w};
            #pragma unroll
            for (int i = 0; i < 4; i++)
                #pragma unroll
                for (int j = 0; j < 4; j++)
                    acc[i][j] = fmaf(m[i], n[j], acc[i][j]);
        }
        __syncthreads();
    }

    #pragma unroll
    for (int i = 0; i < 4; i++) {
        int gr = brow * BM + trow * 4 + i;
        if (gr < NN) {
            float4 v = make_float4(acc[i][0], acc[i][1], acc[i][2], acc[i][3]);
            *reinterpret_cast<float4*>(g_xh + (size_t)gr * HC + bcol * BN + tcol * 4) = v;
        }
    }
}

// -------- K2: per-node attention logits (warp per node) --------
__global__ __launch_bounds__(256) void logits_kernel(
    const float* __restrict__ att_src, const float* __restrict__ att_dst)
{
    int warp = (blockIdx.x * blockDim.x + threadIdx.x) >> 5;
    int lane = threadIdx.x & 31;
    if (warp >= NN) return;

    // lane handles cols [lane*8, lane*8+8); head = lane/8 (8 lanes per head)
    const float4* xr = reinterpret_cast<const float4*>(g_xh + (size_t)warp * HC);
    float4 v0 = xr[lane * 2];
    float4 v1 = xr[lane * 2 + 1];

    int h    = lane >> 3;
    int coff = (lane & 7) * 8;
    const float* as = att_src + h * OUTC + coff;
    const float* ad = att_dst + h * OUTC + coff;

    float ps = v0.x * __ldg(as + 0) + v0.y * __ldg(as + 1) + v0.z * __ldg(as + 2) + v0.w * __ldg(as + 3)
             + v1.x * __ldg(as + 4) + v1.y * __ldg(as + 5) + v1.z * __ldg(as + 6) + v1.w * __ldg(as + 7);
    float pd = v0.x * __ldg(ad + 0) + v0.y * __ldg(ad + 1) + v0.z * __ldg(ad + 2) + v0.w * __ldg(ad + 3)
             + v1.x * __ldg(ad + 4) + v1.y * __ldg(ad + 5) + v1.z * __ldg(ad + 6) + v1.w * __ldg(ad + 7);

    #pragma unroll
    for (int o = 4; o >= 1; o >>= 1) {
        ps += __shfl_xor_sync(0xffffffffu, ps, o);
        pd += __shfl_xor_sync(0xffffffffu, pd, o);
    }
    if ((lane & 7) == 0) {
        g_asrc[warp * HH + h] = ps;
        g_adst[warp * HH + h] = pd;
    }
}

// -------- K3: segment max over incoming edges (thread per edge) --------
__global__ __launch_bounds__(256) void edgemax_kernel(const int* __restrict__ ei)
{
    int e = blockIdx.x * blockDim.x + threadIdx.x;
    if (e >= EE + NN) return;
    int s, d;
    if (e < EE) { s = __ldg(ei + e); d = __ldg(ei + EE + e); }
    else        { s = e - EE; d = s; }

    float4 As = *reinterpret_cast<const float4*>(g_asrc + s * HH);
    float4 Ad = *reinterpret_cast<const float4*>(g_adst + d * HH);
    float a0 = leaky(As.x + Ad.x);
    float a1 = leaky(As.y + Ad.y);
    float a2 = leaky(As.z + Ad.z);
    float a3 = leaky(As.w + Ad.w);
    atomicMax(&g_amax[d * HH + 0], enc_f(a0));
    atomicMax(&g_amax[d * HH + 1], enc_f(a1));
    atomicMax(&g_amax[d * HH + 2], enc_f(a2));
    atomicMax(&g_amax[d * HH + 3], enc_f(a3));
}

// -------- K4: exp + denom + unnormalized weighted scatter (warp per edge) --------
__global__ __launch_bounds__(256) void edgeacc_kernel(const int* __restrict__ ei)
{
    int warp = (blockIdx.x * blockDim.x + threadIdx.x) >> 5;
    int lane = threadIdx.x & 31;
    if (warp >= EE + NN) return;

    int s, d;
    if (warp < EE) { s = __ldg(ei + warp); d = __ldg(ei + EE + warp); }
    else           { s = warp - EE; d = s; }

    // lanes 0..3 compute exp weight for their head, add to denom
    float myw = 0.f;
    if (lane < HH) {
        float a = g_asrc[s * HH + lane] + g_adst[d * HH + lane];
        a = leaky(a);
        float m = dec_f(g_amax[d * HH + lane]);
        myw = __expf(a - m);
        atomicAdd(&g_denom[d * HH + lane], myw);
    }
    // chunk i (float4 units in [0,64)): head = i/16. lane handles i=lane and i=lane+32.
    float w0 = __shfl_sync(0xffffffffu, myw, lane >> 4);
    float w1 = __shfl_sync(0xffffffffu, myw, (lane >> 4) + 2);

    const float4* xr = reinterpret_cast<const float4*>(g_xh) + (size_t)s * (HC / 4);
    float4*       ar = reinterpret_cast<float4*>(g_accum)    + (size_t)d * (HC / 4);

    float4 v0 = xr[lane];
    float4 v1 = xr[lane + 32];
    asm volatile("red.global.add.v4.f32 [%0], {%1,%2,%3,%4};"
                 :: "l"(ar + lane),
                    "f"(v0.x * w0), "f"(v0.y * w0), "f"(v0.z * w0), "f"(v0.w * w0)
                 : "memory");
    asm volatile("red.global.add.v4.f32 [%0], {%1,%2,%3,%4};"
                 :: "l"(ar + lane + 32),
                    "f"(v1.x * w1), "f"(v1.y * w1), "f"(v1.z * w1), "f"(v1.w * w1)
                 : "memory");
}

// -------- K5: normalize per head, mean over heads, biases, relu --------
__global__ __launch_bounds__(256) void finalize_kernel(
    const float* __restrict__ cb, const float* __restrict__ lb, float* __restrict__ out)
{
    int idx = blockIdx.x * blockDim.x + threadIdx.x;
    if (idx >= NN * OUTC) return;
    int n = idx >> 6;
    int c = idx & 63;

    float sum = 0.f;
    #pragma unroll
    for (int h = 0; h < HH; h++) {
        float den = g_denom[n * HH + h] + 1e-16f;
        sum += g_accum[(size_t)n * HC + h * OUTC + c] / den;
    }
    float v = sum * (1.f / HH) + __ldg(cb + c) + __ldg(lb + c);
    out[idx] = v > 0.f ? v : 0.f;
}

// -------- launch --------
extern "C" void kernel_launch(void* const* d_in, const int* in_sizes, int n_in,
                              void* d_out, int out_size)
{
    const float* x     = (const float*)d_in[0];
    const int*   ei    = (const int*)  d_in[1];
    const float* w     = (const float*)d_in[2];
    const float* att_s = (const float*)d_in[3];
    const float* att_d = (const float*)d_in[4];
    const float* cb    = (const float*)d_in[5];
    const float* lb    = (const float*)d_in[6];
    float* out = (float*)d_out;

    init_kernel<<<2048, 256>>>();
    gemm_kernel<<<dim3(HC / BN, (NN + BM - 1) / BM), 256>>>(x, w);
    logits_kernel<<<(NN * 32 + 255) / 256, 256>>>(att_s, att_d);
    edgemax_kernel<<<(EE + NN + 255) / 256, 256>>>(ei);
    edgeacc_kernel<<<((EE + NN) * 32 + 255) / 256, 256>>>(ei);
    finalize_kernel<<<(NN * OUTC + 255) / 256, 256>>>(cb, lb, out);
}

// round 2
// speedup vs baseline: 1.5288x; 1.5288x over previous
#include <cuda_runtime.h>
#include <cuda_bf16.h>
#include <cstdint>

#define NN   50000
#define EE   800000
#define INC  128
#define OUTC 64
#define HH   4
#define HC   (HH*OUTC)   // 256
#define NEG  0.2f
#define SCAN_BLOCKS ((NN + 1023) / 1024)

// -------- scratch --------
__device__ __align__(16) float g_xh[(size_t)NN * HC];   // projected features [N,H,C]
__device__ __align__(16) float g_asrc[NN * HH];
__device__ __align__(16) float g_adst[NN * HH];
__device__ int g_deg[NN];          // in-degree (real edges only)
__device__ int g_loc[NN];          // block-local exclusive scan
__device__ int g_off[NN];          // CSR start offsets
__device__ int g_cur[NN];          // scatter cursors
__device__ int g_eidx[EE];         // src node per CSR slot
__device__ int g_bsum[SCAN_BLOCKS];

__device__ __forceinline__ float leaky(float a) { return a > 0.f ? a : NEG * a; }

// -------- K0: zero degree counters --------
__global__ void zero_kernel() {
    int i = blockIdx.x * blockDim.x + threadIdx.x;
    if (i < NN) g_deg[i] = 0;
}

// -------- K1: SGEMM  xh = x[N,128] @ W[128,256] --------
#define BM 64
#define BN 64
#define BK 16
__global__ __launch_bounds__(256) void gemm_kernel(
    const float* __restrict__ A, const float* __restrict__ B)
{
    __shared__ float As[BK][BM];
    __shared__ float Bs[BK][BN];

    const int brow = blockIdx.y;
    const int bcol = blockIdx.x;
    const int tid  = threadIdx.x;
    const int tcol = tid & 15;
    const int trow = tid >> 4;

    const int rowA  = tid >> 2;
    const int colA4 = tid & 3;
    const int rowB  = tid >> 4;
    const int colB4 = tid & 15;

    float acc[4][4];
    #pragma unroll
    for (int i = 0; i < 4; i++)
        #pragma unroll
        for (int j = 0; j < 4; j++) acc[i][j] = 0.f;

    const int grA = brow * BM + rowA;

    for (int k0 = 0; k0 < INC; k0 += BK) {
        float4 av = make_float4(0.f, 0.f, 0.f, 0.f);
        if (grA < NN)
            av = *reinterpret_cast<const float4*>(A + (size_t)grA * INC + k0 + colA4 * 4);
        As[colA4 * 4 + 0][rowA] = av.x;
        As[colA4 * 4 + 1][rowA] = av.y;
        As[colA4 * 4 + 2][rowA] = av.z;
        As[colA4 * 4 + 3][rowA] = av.w;

        float4 bv = *reinterpret_cast<const float4*>(
            B + (size_t)(k0 + rowB) * HC + bcol * BN + colB4 * 4);
        *reinterpret_cast<float4*>(&Bs[rowB][colB4 * 4]) = bv;

        __syncthreads();

        #pragma unroll
        for (int k = 0; k < BK; k++) {
            float4 rm = *reinterpret_cast<const float4*>(&As[k][trow * 4]);
            float4 rn = *reinterpret_cast<const float4*>(&Bs[k][tcol * 4]);
            float m[4] = {rm.x, rm.y, rm.z, rm.w};
            float n[4] = {rn.x, rn.y, rn.z, rn.w};
            #pragma unroll
            for (int i = 0; i < 4; i++)
                #pragma unroll
                for (int j = 0; j < 4; j++)
                    acc[i][j] = fmaf(m[i], n[j], acc[i][j]);
        }
        __syncthreads();
    }

    #pragma unroll
    for (int i = 0; i < 4; i++) {
        int gr = brow * BM + trow * 4 + i;
        if (gr < NN) {
            float4 v = make_float4(acc[i][0], acc[i][1], acc[i][2], acc[i][3]);
            *reinterpret_cast<float4*>(g_xh + (size_t)gr * HC + bcol * BN + tcol * 4) = v;
        }
    }
}

// -------- K2: per-node attention logits (warp per node) --------
__global__ __launch_bounds__(256) void logits_kernel(
    const float* __restrict__ att_src, const float* __restrict__ att_dst)
{
    int warp = (blockIdx.x * blockDim.x + threadIdx.x) >> 5;
    int lane = threadIdx.x & 31;
    if (warp >= NN) return;

    const float4* xr = reinterpret_cast<const float4*>(g_xh + (size_t)warp * HC);
    float4 v0 = xr[lane * 2];
    float4 v1 = xr[lane * 2 + 1];

    int h    = lane >> 3;
    int coff = (lane & 7) * 8;
    const float* as = att_src + h * OUTC + coff;
    const float* ad = att_dst + h * OUTC + coff;

    float ps = v0.x * __ldg(as + 0) + v0.y * __ldg(as + 1) + v0.z * __ldg(as + 2) + v0.w * __ldg(as + 3)
             + v1.x * __ldg(as + 4) + v1.y * __ldg(as + 5) + v1.z * __ldg(as + 6) + v1.w * __ldg(as + 7);
    float pd = v0.x * __ldg(ad + 0) + v0.y * __ldg(ad + 1) + v0.z * __ldg(ad + 2) + v0.w * __ldg(ad + 3)
             + v1.x * __ldg(ad + 4) + v1.y * __ldg(ad + 5) + v1.z * __ldg(ad + 6) + v1.w * __ldg(ad + 7);

    #pragma unroll
    for (int o = 4; o >= 1; o >>= 1) {
        ps += __shfl_xor_sync(0xffffffffu, ps, o);
        pd += __shfl_xor_sync(0xffffffffu, pd, o);
    }
    if ((lane & 7) == 0) {
        g_asrc[warp * HH + h] = ps;
        g_adst[warp * HH + h] = pd;
    }
}

// -------- K3: in-degree histogram --------
__global__ __launch_bounds__(256) void hist_kernel(const int* __restrict__ ei) {
    int e = blockIdx.x * blockDim.x + threadIdx.x;
    if (e >= EE) return;
    atomicAdd(&g_deg[__ldg(ei + EE + e)], 1);
}

// -------- K4a: block-level exclusive scan --------
__global__ __launch_bounds__(1024) void scan1_kernel() {
    __shared__ int sh[1024];
    int tid = threadIdx.x;
    int i = blockIdx.x * 1024 + tid;
    int v = (i < NN) ? g_deg[i] : 0;
    sh[tid] = v;
    __syncthreads();
    #pragma unroll
    for (int o = 1; o < 1024; o <<= 1) {
        int t = (tid >= o) ? sh[tid - o] : 0;
        __syncthreads();
        sh[tid] += t;
        __syncthreads();
    }
    int incl = sh[tid];
    if (i < NN) g_loc[i] = incl - v;
    if (tid == 1023) g_bsum[blockIdx.x] = incl;
}

// -------- K4b: scan of block sums (in place, exclusive) --------
__global__ void scan2_kernel() {
    if (threadIdx.x == 0) {
        int run = 0;
        for (int k = 0; k < SCAN_BLOCKS; k++) {
            int t = g_bsum[k];
            g_bsum[k] = run;
            run += t;
        }
    }
}

// -------- K4c: global offsets + cursors --------
__global__ __launch_bounds__(256) void scan3_kernel() {
    int i = blockIdx.x * blockDim.x + threadIdx.x;
    if (i >= NN) return;
    int off = g_loc[i] + g_bsum[i >> 10];
    g_off[i] = off;
    g_cur[i] = off;
}

// -------- K5: scatter edges into CSR --------
__global__ __launch_bounds__(256) void scatter_kernel(const int* __restrict__ ei) {
    int e = blockIdx.x * blockDim.x + threadIdx.x;
    if (e >= EE) return;
    int s = __ldg(ei + e);
    int d = __ldg(ei + EE + e);
    int pos = atomicAdd(&g_cur[d], 1);
    g_eidx[pos] = s;
}

// -------- K6: fused gather + softmax + head-mean + bias + relu (warp per dst) --------
__global__ __launch_bounds__(256) void aggregate_kernel(
    const float* __restrict__ cb, const float* __restrict__ lb, float* __restrict__ out)
{
    const unsigned FULL = 0xffffffffu;
    int warp = (blockIdx.x * blockDim.x + threadIdx.x) >> 5;
    int lane = threadIdx.x & 31;
    if (warp >= NN) return;

    const int d   = warp;
    const int off = g_off[d];
    const int len = g_deg[d];

    // each lane "owns" head (lane&3) for logit/exp work
    const int   myh    = lane & 3;
    const float adst_h = g_adst[d * HH + myh];

    // chunk heads for this lane's two float4 accumulators
    const int h0 = lane >> 4;       // 0 or 1
    const int h1 = 2 + (lane >> 4); // 2 or 3

    float4 acc0 = make_float4(0.f, 0.f, 0.f, 0.f);
    float4 acc1 = make_float4(0.f, 0.f, 0.f, 0.f);
    float  den  = 0.f;   // valid for head=lane in lanes 0..3

    // j == off-1 encodes the implicit self-loop (s = d)
    for (int j = off - 1; j < off + len; j++) {
        int s = (j < off) ? d : __ldg(g_eidx + j);

        float a = g_asrc[s * HH + myh] + adst_h;
        float w = __expf(leaky(a));
        if (lane < HH) den += w;

        float w0 = __shfl_sync(FULL, w, h0);
        float w1 = __shfl_sync(FULL, w, h1);

        const float4* xr = reinterpret_cast<const float4*>(g_xh) + (size_t)s * (HC / 4);
        float4 v0 = xr[lane];
        float4 v1 = xr[lane + 32];
        acc0.x = fmaf(w0, v0.x, acc0.x);
        acc0.y = fmaf(w0, v0.y, acc0.y);
        acc0.z = fmaf(w0, v0.z, acc0.z);
        acc0.w = fmaf(w0, v0.w, acc0.w);
        acc1.x = fmaf(w1, v1.x, acc1.x);
        acc1.y = fmaf(w1, v1.y, acc1.y);
        acc1.z = fmaf(w1, v1.z, acc1.z);
        acc1.w = fmaf(w1, v1.w, acc1.w);
    }

    // reciprocal denominators, broadcast from lanes 0..3
    float rden = (lane < HH) ? (1.f / den) : 0.f;
    float r0 = __shfl_sync(FULL, rden, h0);
    float r1 = __shfl_sync(FULL, rden, h1);

    // per-lane partial of the head-mean: heads {h0, h1}
    float4 p;
    p.x = acc0.x * r0 + acc1.x * r1;
    p.y = acc0.y * r0 + acc1.y * r1;
    p.z = acc0.z * r0 + acc1.z * r1;
    p.w = acc0.w * r0 + acc1.w * r1;

    // lane L and lane L^16 hold the other two heads for the same channels
    p.x += __shfl_xor_sync(FULL, p.x, 16);
    p.y += __shfl_xor_sync(FULL, p.y, 16);
    p.z += __shfl_xor_sync(FULL, p.z, 16);
    p.w += __shfl_xor_sync(FULL, p.w, 16);

    if (lane < 16) {
        int c = lane * 4;
        float b0 = __ldg(cb + c + 0) + __ldg(lb + c + 0);
        float b1 = __ldg(cb + c + 1) + __ldg(lb + c + 1);
        float b2 = __ldg(cb + c + 2) + __ldg(lb + c + 2);
        float b3 = __ldg(cb + c + 3) + __ldg(lb + c + 3);
        float4 o;
        o.x = fmaf(p.x, 0.25f, b0); o.x = o.x > 0.f ? o.x : 0.f;
        o.y = fmaf(p.y, 0.25f, b1); o.y = o.y > 0.f ? o.y : 0.f;
        o.z = fmaf(p.z, 0.25f, b2); o.z = o.z > 0.f ? o.z : 0.f;
        o.w = fmaf(p.w, 0.25f, b3); o.w = o.w > 0.f ? o.w : 0.f;
        *reinterpret_cast<float4*>(out + (size_t)d * OUTC + c) = o;
    }
}

// -------- launch --------
extern "C" void kernel_launch(void* const* d_in, const int* in_sizes, int n_in,
                              void* d_out, int out_size)
{
    const float* x     = (const float*)d_in[0];
    const int*   ei    = (const int*)  d_in[1];
    const float* w     = (const float*)d_in[2];
    const float* att_s = (const float*)d_in[3];
    const float* att_d = (const float*)d_in[4];
    const float* cb    = (const float*)d_in[5];
    const float* lb    = (const float*)d_in[6];
    float* out = (float*)d_out;

    zero_kernel<<<(NN + 255) / 256, 256>>>();
    gemm_kernel<<<dim3(HC / BN, (NN + BM - 1) / BM), 256>>>(x, w);
    logits_kernel<<<(NN * 32 + 255) / 256, 256>>>(att_s, att_d);
    hist_kernel<<<(EE + 255) / 256, 256>>>(ei);
    scan1_kernel<<<SCAN_BLOCKS, 1024>>>();
    scan2_kernel<<<1, 32>>>();
    scan3_kernel<<<(NN + 255) / 256, 256>>>();
    scatter_kernel<<<(EE + 255) / 256, 256>>>(ei);
    aggregate_kernel<<<(NN * 32 + 255) / 256, 256>>>(cb, lb, out);
}

// round 4
// speedup vs baseline: 2.1910x; 1.4331x over previous
#include <cuda_runtime.h>
#include <cuda_fp16.h>
#include <cstdint>

#define NN   50000
#define EE   800000
#define INC  128
#define OUTC 64
#define HH   4
#define HC   (HH*OUTC)   // 256
#define NEG  0.2f
#define SCAN_BLOCKS ((NN + 1023) / 1024)

// -------- scratch --------
__device__ __align__(16) __half g_xhh[(size_t)NN * HC]; // projected features, fp16 [N][256]
__device__ __align__(16) float g_asrc[NN * HH];
__device__ __align__(16) float g_adst[NN * HH];
__device__ int g_deg[NN];
__device__ int g_loc[NN];
__device__ int g_off[NN];
__device__ int g_cur[NN];
__device__ int g_eidx[EE];
__device__ int g_bsum[SCAN_BLOCKS];

__device__ __forceinline__ float leaky(float a) { return a > 0.f ? a : NEG * a; }

__device__ __forceinline__ unsigned f2tf(float f) {
    unsigned u; asm("cvt.rna.tf32.f32 %0, %1;" : "=r"(u) : "f"(f)); return u;
}
__device__ __forceinline__ void mma8(float* c, const unsigned* a, unsigned b0, unsigned b1) {
    asm("mma.sync.aligned.m16n8k8.row.col.f32.tf32.tf32.f32 "
        "{%0,%1,%2,%3},{%4,%5,%6,%7},{%8,%9},{%0,%1,%2,%3};"
        : "+f"(c[0]), "+f"(c[1]), "+f"(c[2]), "+f"(c[3])
        : "r"(a[0]), "r"(a[1]), "r"(a[2]), "r"(a[3]), "r"(b0), "r"(b1));
}

// -------- K0: zero degree counters --------
__global__ void zero_kernel() {
    int i = blockIdx.x * blockDim.x + threadIdx.x;
    if (i < NN) g_deg[i] = 0;
}

// -------- K1: fused 3xTF32 GEMM + fp16 xh + per-head logits --------
// grid (4 heads, 391 row-tiles), 256 threads. Block: rows[brow*128,+128) x head bcol (64 cols).
#define GBM 128
#define GBN 64
#define GBK 16
#define AROW 44   // u32 row stride of sA: hi at +0..15, lo at +22..37; 44*g%32=12g%32 distinct
#define BSTR 72   // 72%32=8 -> tig*8+g distinct banks
__global__ __launch_bounds__(256) void gemm_kernel(
    const float* __restrict__ A, const float* __restrict__ B,
    const float* __restrict__ attS, const float* __restrict__ attD)
{
    __shared__ __align__(16) unsigned sA[GBM * AROW];   // A hi/lo planes; reused as fp16 out stage
    __shared__ __align__(16) unsigned sBh[GBK * BSTR];
    __shared__ __align__(16) unsigned sBl[GBK * BSTR];
    __shared__ float sLS[GBM * 2];
    __shared__ float sLD[GBM * 2];

    const int brow = blockIdx.y, bcol = blockIdx.x;
    const int tid  = threadIdx.x;
    const int lane = tid & 31;
    const int warp = tid >> 5;
    const int wm = warp >> 1, wn = warp & 1;   // 4 x 2 warp grid (32x32 per warp)
    const int g = lane >> 2, tig = lane & 3;

    float acc[2][4][4];
    #pragma unroll
    for (int mt = 0; mt < 2; mt++)
        #pragma unroll
        for (int nt = 0; nt < 4; nt++)
            #pragma unroll
            for (int i = 0; i < 4; i++) acc[mt][nt][i] = 0.f;

    for (int k0 = 0; k0 < INC; k0 += GBK) {
        // A tile: 128 rows x 16 cols, 2 float4 per thread
        #pragma unroll
        for (int p = 0; p < 2; p++) {
            int idx = p * 256 + tid;
            int r = idx >> 2, c4 = (idx & 3) * 4;
            int grow = brow * GBM + r;
            float4 v = make_float4(0.f, 0.f, 0.f, 0.f);
            if (grow < NN)
                v = *reinterpret_cast<const float4*>(A + (size_t)grow * INC + k0 + c4);
            unsigned* dh = &sA[r * AROW + c4];
            unsigned* dl = dh + 22;
            const float* pf = &v.x;
            #pragma unroll
            for (int q = 0; q < 4; q++) {
                unsigned hi = f2tf(pf[q]);
                dh[q] = hi;
                dl[q] = f2tf(pf[q] - __uint_as_float(hi));
            }
        }
        // B tile: 16 rows x 64 cols, 1 float4 per thread
        {
            int r = tid >> 4, c4 = (tid & 15) * 4;
            float4 v = *reinterpret_cast<const float4*>(
                B + (size_t)(k0 + r) * HC + bcol * GBN + c4);
            unsigned* dh = &sBh[r * BSTR + c4];
            unsigned* dl = &sBl[r * BSTR + c4];
            const float* pf = &v.x;
            #pragma unroll
            for (int q = 0; q < 4; q++) {
                unsigned hi = f2tf(pf[q]);
                dh[q] = hi;
                dl[q] = f2tf(pf[q] - __uint_as_float(hi));
            }
        }
        __syncthreads();

        #pragma unroll
        for (int kk = 0; kk < GBK; kk += 8) {
            unsigned afh[2][4], afl[2][4];
            #pragma unroll
            for (int mt = 0; mt < 2; mt++) {
                int rb = wm * 32 + mt * 16;
                #pragma unroll
                for (int q = 0; q < 4; q++) {
                    int rr = rb + g + (q & 1) * 8;
                    int cc = kk + tig + (q >> 1) * 4;
                    afh[mt][q] = sA[rr * AROW + cc];
                    afl[mt][q] = sA[rr * AROW + 22 + cc];
                }
            }
            #pragma unroll
            for (int nt = 0; nt < 4; nt++) {
                int cb = wn * 32 + nt * 8 + g;
                unsigned b0h = sBh[(kk + tig)     * BSTR + cb];
                unsigned b1h = sBh[(kk + tig + 4) * BSTR + cb];
                unsigned b0l = sBl[(kk + tig)     * BSTR + cb];
                unsigned b1l = sBl[(kk + tig + 4) * BSTR + cb];
                #pragma unroll
                for (int mt = 0; mt < 2; mt++) {
                    mma8(acc[mt][nt], afl[mt], b0h, b1h);
                    mma8(acc[mt][nt], afh[mt], b0l, b1l);
                    mma8(acc[mt][nt], afh[mt], b0h, b1h);
                }
            }
        }
        __syncthreads();
    }

    // ---- epilogue: per-head logit partials from fp32 accumulators ----
    float aS[4][2], aD[4][2];
    #pragma unroll
    for (int nt = 0; nt < 4; nt++) {
        int col0 = wn * 32 + nt * 8 + 2 * tig;
        aS[nt][0] = __ldg(attS + bcol * OUTC + col0);
        aS[nt][1] = __ldg(attS + bcol * OUTC + col0 + 1);
        aD[nt][0] = __ldg(attD + bcol * OUTC + col0);
        aD[nt][1] = __ldg(attD + bcol * OUTC + col0 + 1);
    }
    float ps[2][2] = {{0.f,0.f},{0.f,0.f}}, pd[2][2] = {{0.f,0.f},{0.f,0.f}};
    #pragma unroll
    for (int mt = 0; mt < 2; mt++)
        #pragma unroll
        for (int nt = 0; nt < 4; nt++) {
            ps[mt][0] += acc[mt][nt][0] * aS[nt][0] + acc[mt][nt][1] * aS[nt][1];
            ps[mt][1] += acc[mt][nt][2] * aS[nt][0] + acc[mt][nt][3] * aS[nt][1];
            pd[mt][0] += acc[mt][nt][0] * aD[nt][0] + acc[mt][nt][1] * aD[nt][1];
            pd[mt][1] += acc[mt][nt][2] * aD[nt][0] + acc[mt][nt][3] * aD[nt][1];
        }
    #pragma unroll
    for (int mt = 0; mt < 2; mt++)
        #pragma unroll
        for (int hf = 0; hf < 2; hf++) {
            ps[mt][hf] += __shfl_xor_sync(0xffffffffu, ps[mt][hf], 1);
            ps[mt][hf] += __shfl_xor_sync(0xffffffffu, ps[mt][hf], 2);
            pd[mt][hf] += __shfl_xor_sync(0xffffffffu, pd[mt][hf], 1);
            pd[mt][hf] += __shfl_xor_sync(0xffffffffu, pd[mt][hf], 2);
        }
    if (tig == 0) {
        #pragma unroll
        for (int mt = 0; mt < 2; mt++)
            #pragma unroll
            for (int hf = 0; hf < 2; hf++) {
                int r = wm * 32 + mt * 16 + hf * 8 + g;
                sLS[r * 2 + wn] = ps[mt][hf];
                sLD[r * 2 + wn] = pd[mt][hf];
            }
    }

    // ---- stage C tile as fp16 into sA (row stride 32 u32 = 64 halves) ----
    __syncthreads();   // planes no longer needed; reuse as staging
    #pragma unroll
    for (int mt = 0; mt < 2; mt++)
        #pragma unroll
        for (int nt = 0; nt < 4; nt++) {
            int r0  = wm * 32 + mt * 16 + g;
            int col = wn * 32 + nt * 8 + 2 * tig;
            __half2 lo = __floats2half2_rn(acc[mt][nt][0], acc[mt][nt][1]);
            __half2 hi = __floats2half2_rn(acc[mt][nt][2], acc[mt][nt][3]);
            sA[r0 * 32 + (col >> 1)]       = *reinterpret_cast<unsigned*>(&lo);
            sA[(r0 + 8) * 32 + (col >> 1)] = *reinterpret_cast<unsigned*>(&hi);
        }
    __syncthreads();

    if (tid < GBM) {
        int grow = brow * GBM + tid;
        if (grow < NN) {
            g_asrc[grow * HH + bcol] = sLS[tid * 2] + sLS[tid * 2 + 1];
            g_adst[grow * HH + bcol] = sLD[tid * 2] + sLD[tid * 2 + 1];
        }
    }
    const uint4* s4 = reinterpret_cast<const uint4*>(sA);
    uint4* o4 = reinterpret_cast<uint4*>(g_xhh);
    #pragma unroll
    for (int p = 0; p < 4; p++) {
        int i = p * 256 + tid;          // uint4 index in 128x(8 uint4) tile
        int r = i >> 3, q = i & 7;
        int grow = brow * GBM + r;
        if (grow < NN)
            o4[(size_t)grow * 32 + bcol * 8 + q] = s4[i];
    }
}

// -------- K3: in-degree histogram (4 edges/thread) --------
__global__ __launch_bounds__(256) void hist_kernel(const int* __restrict__ ei) {
    int t = blockIdx.x * blockDim.x + threadIdx.x;
    if (t * 4 >= EE) return;
    int4 d4 = __ldg(reinterpret_cast<const int4*>(ei + EE) + t);
    atomicAdd(&g_deg[d4.x], 1);
    atomicAdd(&g_deg[d4.y], 1);
    atomicAdd(&g_deg[d4.z], 1);
    atomicAdd(&g_deg[d4.w], 1);
}

// -------- K4a: block-level scan --------
__global__ __launch_bounds__(1024) void scan1_kernel() {
    __shared__ int sh[1024];
    int tid = threadIdx.x;
    int i = blockIdx.x * 1024 + tid;
    int v = (i < NN) ? g_deg[i] : 0;
    sh[tid] = v;
    __syncthreads();
    #pragma unroll
    for (int o = 1; o < 1024; o <<= 1) {
        int t = (tid >= o) ? sh[tid - o] : 0;
        __syncthreads();
        sh[tid] += t;
        __syncthreads();
    }
    int incl = sh[tid];
    if (i < NN) g_loc[i] = incl - v;
    if (tid == 1023) g_bsum[blockIdx.x] = incl;
}

// -------- K4b: serial scan of block sums --------
__global__ void scan2_kernel() {
    if (threadIdx.x == 0) {
        int run = 0;
        for (int k = 0; k < SCAN_BLOCKS; k++) {
            int t = g_bsum[k]; g_bsum[k] = run; run += t;
        }
    }
}

// -------- K4c: global offsets + cursors --------
__global__ __launch_bounds__(256) void scan3_kernel() {
    int i = blockIdx.x * blockDim.x + threadIdx.x;
    if (i >= NN) return;
    int off = g_loc[i] + g_bsum[i >> 10];
    g_off[i] = off;
    g_cur[i] = off;
}

// -------- K5: scatter edges into CSR (4 edges/thread) --------
__global__ __launch_bounds__(256) void scatter_kernel(const int* __restrict__ ei) {
    int t = blockIdx.x * blockDim.x + threadIdx.x;
    if (t * 4 >= EE) return;
    int4 s4 = __ldg(reinterpret_cast<const int4*>(ei) + t);
    int4 d4 = __ldg(reinterpret_cast<const int4*>(ei + EE) + t);
    g_eidx[atomicAdd(&g_cur[d4.x], 1)] = s4.x;
    g_eidx[atomicAdd(&g_cur[d4.y], 1)] = s4.y;
    g_eidx[atomicAdd(&g_cur[d4.z], 1)] = s4.z;
    g_eidx[atomicAdd(&g_cur[d4.w], 1)] = s4.w;
}

// -------- K6: fused fp16 gather + softmax + head-mean + bias + relu (warp per dst) --------
__global__ __launch_bounds__(256) void aggregate_kernel(
    const float* __restrict__ cb, const float* __restrict__ lb, float* __restrict__ out)
{
    const unsigned FULL = 0xffffffffu;
    int warpid = (blockIdx.x * blockDim.x + threadIdx.x) >> 5;
    int lane = threadIdx.x & 31;
    if (warpid >= NN) return;

    const int d   = warpid;
    const int off = g_off[d];
    const int jend = off + g_deg[d];

    const int hl = lane >> 3;                      // head owned by this lane's channels
    const float adh = __ldg(g_adst + d * HH + hl);

    float acc[8];
    #pragma unroll
    for (int i = 0; i < 8; i++) acc[i] = 0.f;
    float den = 0.f;

    const uint4* xb = reinterpret_cast<const uint4*>(g_xhh);

    int s = d;  // first iteration = implicit self-loop
    for (int j = off - 1; j < jend; j++) {
        int snext = (j + 1 < jend) ? __ldg(g_eidx + j + 1) : 0;

        float a = __ldg(g_asrc + s * HH + hl) + adh;
        float w = __expf(leaky(a));
        if ((lane & 7) == 0) den += w;

        uint4 v = xb[(size_t)s * 32 + lane];
        const __half2* pv = reinterpret_cast<const __half2*>(&v);
        #pragma unroll
        for (int q = 0; q < 4; q++) {
            float2 f = __half22float2(pv[q]);
            acc[2 * q]     = fmaf(w, f.x, acc[2 * q]);
            acc[2 * q + 1] = fmaf(w, f.y, acc[2 * q + 1]);
        }
        s = snext;
    }

    float r = ((lane & 7) == 0) ? (1.f / den) : 0.f;
    r = __shfl_sync(FULL, r, lane & 24);

    float o[8];
    #pragma unroll
    for (int i = 0; i < 8; i++) {
        float v = acc[i] * r;
        v += __shfl_xor_sync(FULL, v, 8);
        v += __shfl_xor_sync(FULL, v, 16);
        o[i] = v;
    }

    if (lane < 8) {
        int c = lane * 8;
        float4 o0, o1;
        #pragma unroll
        for (int i = 0; i < 8; i++) {
            float b = __ldg(cb + c + i) + __ldg(lb + c + i);
            float v = fmaf(o[i], 0.25f, b);
            v = v > 0.f ? v : 0.f;
            if (i < 4) (&o0.x)[i] = v; else (&o1.x)[i - 4] = v;
        }
        float4* po4 = reinterpret_cast<float4*>(out + (size_t)d * OUTC + c);
        po4[0] = o0;
        po4[1] = o1;
    }
}

// -------- launch --------
extern "C" void kernel_launch(void* const* d_in, const int* in_sizes, int n_in,
                              void* d_out, int out_size)
{
    const float* x     = (const float*)d_in[0];
    const int*   ei    = (const int*)  d_in[1];
    const float* w     = (const float*)d_in[2];
    const float* att_s = (const float*)d_in[3];
    const float* att_d = (const float*)d_in[4];
    const float* cb    = (const float*)d_in[5];
    const float* lb    = (const float*)d_in[6];
    float* out = (float*)d_out;

    zero_kernel<<<(NN + 255) / 256, 256>>>();
    gemm_kernel<<<dim3(HC / GBN, (NN + GBM - 1) / GBM), 256>>>(x, w, att_s, att_d);
    hist_kernel<<<(EE / 4 + 255) / 256, 256>>>(ei);
    scan1_kernel<<<SCAN_BLOCKS, 1024>>>();
    scan2_kernel<<<1, 32>>>();
    scan3_kernel<<<(NN + 255) / 256, 256>>>();
    scatter_kernel<<<(EE / 4 + 255) / 256, 256>>>(ei);
    aggregate_kernel<<<(NN * 32 + 255) / 256, 256>>>(cb, lb, out);
}

// round 5
// speedup vs baseline: 2.3516x; 1.0733x over previous
#include <cuda_runtime.h>
#include <cuda_fp16.h>
#include <cstdint>

#define NN   50000
#define EE   800000
#define INC  128
#define OUTC 64
#define HH   4
#define HC   (HH*OUTC)   // 256
#define NEG  0.2f
#define SCAN_BLOCKS ((NN + 1023) / 1024)

// -------- scratch --------
__device__ __align__(16) __half g_xhh[(size_t)NN * HC]; // projected features, fp16 [N][256]
__device__ __align__(16) float g_asrc[NN * HH];
__device__ __align__(16) float g_adst[NN * HH];
__device__ int g_deg[NN];
__device__ int g_loc[NN];
__device__ int g_off[NN];
__device__ int g_cur[NN];
__device__ int g_eidx[EE];
__device__ int g_bsum[SCAN_BLOCKS];

__device__ __forceinline__ float leaky(float a) { return a > 0.f ? a : NEG * a; }

__device__ __forceinline__ unsigned f2tf(float f) {
    unsigned u; asm("cvt.rna.tf32.f32 %0, %1;" : "=r"(u) : "f"(f)); return u;
}
__device__ __forceinline__ void mma8(float* c, const unsigned* a, unsigned b0, unsigned b1) {
    asm("mma.sync.aligned.m16n8k8.row.col.f32.tf32.tf32.f32 "
        "{%0,%1,%2,%3},{%4,%5,%6,%7},{%8,%9},{%0,%1,%2,%3};"
        : "+f"(c[0]), "+f"(c[1]), "+f"(c[2]), "+f"(c[3])
        : "r"(a[0]), "r"(a[1]), "r"(a[2]), "r"(a[3]), "r"(b0), "r"(b1));
}

// -------- K0: zero degree counters --------
__global__ void zero_kernel() {
    int i = blockIdx.x * blockDim.x + threadIdx.x;
    if (i < NN) g_deg[i] = 0;
}

// -------- K1: fused 3xTF32 GEMM + fp16 xh + per-head logits --------
#define GBM 128
#define GBN 64
#define GBK 16
#define AROW 44   // u32 row stride of sA: hi at +0..15, lo at +22..37
#define BSTR 72
__global__ __launch_bounds__(256) void gemm_kernel(
    const float* __restrict__ A, const float* __restrict__ B,
    const float* __restrict__ attS, const float* __restrict__ attD)
{
    __shared__ __align__(16) unsigned sA[GBM * AROW];   // A hi/lo planes; reused as fp16 out stage
    __shared__ __align__(16) unsigned sBh[GBK * BSTR];
    __shared__ __align__(16) unsigned sBl[GBK * BSTR];
    __shared__ float sLS[GBM * 2];
    __shared__ float sLD[GBM * 2];

    const int brow = blockIdx.y, bcol = blockIdx.x;
    const int tid  = threadIdx.x;
    const int lane = tid & 31;
    const int warp = tid >> 5;
    const int wm = warp >> 1, wn = warp & 1;
    const int g = lane >> 2, tig = lane & 3;

    float acc[2][4][4];
    #pragma unroll
    for (int mt = 0; mt < 2; mt++)
        #pragma unroll
        for (int nt = 0; nt < 4; nt++)
            #pragma unroll
            for (int i = 0; i < 4; i++) acc[mt][nt][i] = 0.f;

    for (int k0 = 0; k0 < INC; k0 += GBK) {
        #pragma unroll
        for (int p = 0; p < 2; p++) {
            int idx = p * 256 + tid;
            int r = idx >> 2, c4 = (idx & 3) * 4;
            int grow = brow * GBM + r;
            float4 v = make_float4(0.f, 0.f, 0.f, 0.f);
            if (grow < NN)
                v = *reinterpret_cast<const float4*>(A + (size_t)grow * INC + k0 + c4);
            unsigned* dh = &sA[r * AROW + c4];
            unsigned* dl = dh + 22;
            const float* pf = &v.x;
            #pragma unroll
            for (int q = 0; q < 4; q++) {
                unsigned hi = f2tf(pf[q]);
                dh[q] = hi;
                dl[q] = f2tf(pf[q] - __uint_as_float(hi));
            }
        }
        {
            int r = tid >> 4, c4 = (tid & 15) * 4;
            float4 v = *reinterpret_cast<const float4*>(
                B + (size_t)(k0 + r) * HC + bcol * GBN + c4);
            unsigned* dh = &sBh[r * BSTR + c4];
            unsigned* dl = &sBl[r * BSTR + c4];
            const float* pf = &v.x;
            #pragma unroll
            for (int q = 0; q < 4; q++) {
                unsigned hi = f2tf(pf[q]);
                dh[q] = hi;
                dl[q] = f2tf(pf[q] - __uint_as_float(hi));
            }
        }
        __syncthreads();

        #pragma unroll
        for (int kk = 0; kk < GBK; kk += 8) {
            unsigned afh[2][4], afl[2][4];
            #pragma unroll
            for (int mt = 0; mt < 2; mt++) {
                int rb = wm * 32 + mt * 16;
                #pragma unroll
                for (int q = 0; q < 4; q++) {
                    int rr = rb + g + (q & 1) * 8;
                    int cc = kk + tig + (q >> 1) * 4;
                    afh[mt][q] = sA[rr * AROW + cc];
                    afl[mt][q] = sA[rr * AROW + 22 + cc];
                }
            }
            #pragma unroll
            for (int nt = 0; nt < 4; nt++) {
                int cb = wn * 32 + nt * 8 + g;
                unsigned b0h = sBh[(kk + tig)     * BSTR + cb];
                unsigned b1h = sBh[(kk + tig + 4) * BSTR + cb];
                unsigned b0l = sBl[(kk + tig)     * BSTR + cb];
                unsigned b1l = sBl[(kk + tig + 4) * BSTR + cb];
                #pragma unroll
                for (int mt = 0; mt < 2; mt++) {
                    mma8(acc[mt][nt], afl[mt], b0h, b1h);
                    mma8(acc[mt][nt], afh[mt], b0l, b1l);
                    mma8(acc[mt][nt], afh[mt], b0h, b1h);
                }
            }
        }
        __syncthreads();
    }

    // ---- epilogue: per-head logit partials ----
    float aS[4][2], aD[4][2];
    #pragma unroll
    for (int nt = 0; nt < 4; nt++) {
        int col0 = wn * 32 + nt * 8 + 2 * tig;
        aS[nt][0] = __ldg(attS + bcol * OUTC + col0);
        aS[nt][1] = __ldg(attS + bcol * OUTC + col0 + 1);
        aD[nt][0] = __ldg(attD + bcol * OUTC + col0);
        aD[nt][1] = __ldg(attD + bcol * OUTC + col0 + 1);
    }
    float ps[2][2] = {{0.f,0.f},{0.f,0.f}}, pd[2][2] = {{0.f,0.f},{0.f,0.f}};
    #pragma unroll
    for (int mt = 0; mt < 2; mt++)
        #pragma unroll
        for (int nt = 0; nt < 4; nt++) {
            ps[mt][0] += acc[mt][nt][0] * aS[nt][0] + acc[mt][nt][1] * aS[nt][1];
            ps[mt][1] += acc[mt][nt][2] * aS[nt][0] + acc[mt][nt][3] * aS[nt][1];
            pd[mt][0] += acc[mt][nt][0] * aD[nt][0] + acc[mt][nt][1] * aD[nt][1];
            pd[mt][1] += acc[mt][nt][2] * aD[nt][0] + acc[mt][nt][3] * aD[nt][1];
        }
    #pragma unroll
    for (int mt = 0; mt < 2; mt++)
        #pragma unroll
        for (int hf = 0; hf < 2; hf++) {
            ps[mt][hf] += __shfl_xor_sync(0xffffffffu, ps[mt][hf], 1);
            ps[mt][hf] += __shfl_xor_sync(0xffffffffu, ps[mt][hf], 2);
            pd[mt][hf] += __shfl_xor_sync(0xffffffffu, pd[mt][hf], 1);
            pd[mt][hf] += __shfl_xor_sync(0xffffffffu, pd[mt][hf], 2);
        }
    if (tig == 0) {
        #pragma unroll
        for (int mt = 0; mt < 2; mt++)
            #pragma unroll
            for (int hf = 0; hf < 2; hf++) {
                int r = wm * 32 + mt * 16 + hf * 8 + g;
                sLS[r * 2 + wn] = ps[mt][hf];
                sLD[r * 2 + wn] = pd[mt][hf];
            }
    }

    // ---- stage C tile as fp16 ----
    __syncthreads();
    #pragma unroll
    for (int mt = 0; mt < 2; mt++)
        #pragma unroll
        for (int nt = 0; nt < 4; nt++) {
            int r0  = wm * 32 + mt * 16 + g;
            int col = wn * 32 + nt * 8 + 2 * tig;
            __half2 lo = __floats2half2_rn(acc[mt][nt][0], acc[mt][nt][1]);
            __half2 hi = __floats2half2_rn(acc[mt][nt][2], acc[mt][nt][3]);
            sA[r0 * 32 + (col >> 1)]       = *reinterpret_cast<unsigned*>(&lo);
            sA[(r0 + 8) * 32 + (col >> 1)] = *reinterpret_cast<unsigned*>(&hi);
        }
    __syncthreads();

    if (tid < GBM) {
        int grow = brow * GBM + tid;
        if (grow < NN) {
            g_asrc[grow * HH + bcol] = sLS[tid * 2] + sLS[tid * 2 + 1];
            g_adst[grow * HH + bcol] = sLD[tid * 2] + sLD[tid * 2 + 1];
        }
    }
    const uint4* s4 = reinterpret_cast<const uint4*>(sA);
    uint4* o4 = reinterpret_cast<uint4*>(g_xhh);
    #pragma unroll
    for (int p = 0; p < 4; p++) {
        int i = p * 256 + tid;
        int r = i >> 3, q = i & 7;
        int grow = brow * GBM + r;
        if (grow < NN)
            o4[(size_t)grow * 32 + bcol * 8 + q] = s4[i];
    }
}

// -------- K3: in-degree histogram (4 edges/thread) --------
__global__ __launch_bounds__(256) void hist_kernel(const int* __restrict__ ei) {
    int t = blockIdx.x * blockDim.x + threadIdx.x;
    if (t * 4 >= EE) return;
    int4 d4 = __ldg(reinterpret_cast<const int4*>(ei + EE) + t);
    atomicAdd(&g_deg[d4.x], 1);
    atomicAdd(&g_deg[d4.y], 1);
    atomicAdd(&g_deg[d4.z], 1);
    atomicAdd(&g_deg[d4.w], 1);
}

// -------- K4a: block-level scan --------
__global__ __launch_bounds__(1024) void scan1_kernel() {
    __shared__ int sh[1024];
    int tid = threadIdx.x;
    int i = blockIdx.x * 1024 + tid;
    int v = (i < NN) ? g_deg[i] : 0;
    sh[tid] = v;
    __syncthreads();
    #pragma unroll
    for (int o = 1; o < 1024; o <<= 1) {
        int t = (tid >= o) ? sh[tid - o] : 0;
        __syncthreads();
        sh[tid] += t;
        __syncthreads();
    }
    int incl = sh[tid];
    if (i < NN) g_loc[i] = incl - v;
    if (tid == 1023) g_bsum[blockIdx.x] = incl;
}

// -------- K4b: one-warp shuffle scan of block sums (exclusive, in place) --------
__global__ void scan2_kernel() {
    int lane = threadIdx.x;
    if (lane >= 32) return;
    int carry = 0;
    #pragma unroll
    for (int base = 0; base < SCAN_BLOCKS; base += 32) {
        int i = base + lane;
        int v = (i < SCAN_BLOCKS) ? g_bsum[i] : 0;
        int incl = v;
        #pragma unroll
        for (int o = 1; o < 32; o <<= 1) {
            int t = __shfl_up_sync(0xffffffffu, incl, o);
            if (lane >= o) incl += t;
        }
        if (i < SCAN_BLOCKS) g_bsum[i] = incl - v + carry;
        carry += __shfl_sync(0xffffffffu, incl, 31);
    }
}

// -------- K4c: global offsets + cursors --------
__global__ __launch_bounds__(256) void scan3_kernel() {
    int i = blockIdx.x * blockDim.x + threadIdx.x;
    if (i >= NN) return;
    int off = g_loc[i] + g_bsum[i >> 10];
    g_off[i] = off;
    g_cur[i] = off;
}

// -------- K5: scatter edges into CSR (4 edges/thread) --------
__global__ __launch_bounds__(256) void scatter_kernel(const int* __restrict__ ei) {
    int t = blockIdx.x * blockDim.x + threadIdx.x;
    if (t * 4 >= EE) return;
    int4 s4 = __ldg(reinterpret_cast<const int4*>(ei) + t);
    int4 d4 = __ldg(reinterpret_cast<const int4*>(ei + EE) + t);
    g_eidx[atomicAdd(&g_cur[d4.x], 1)] = s4.x;
    g_eidx[atomicAdd(&g_cur[d4.y], 1)] = s4.y;
    g_eidx[atomicAdd(&g_cur[d4.z], 1)] = s4.z;
    g_eidx[atomicAdd(&g_cur[d4.w], 1)] = s4.w;
}

// -------- K6: fused fp16 gather + softmax + head-mean + bias + relu --------
__global__ __launch_bounds__(256) void aggregate_kernel(
    const float* __restrict__ cb, const float* __restrict__ lb, float* __restrict__ out)
{
    const unsigned FULL = 0xffffffffu;
    int warpid = (blockIdx.x * blockDim.x + threadIdx.x) >> 5;
    int lane = threadIdx.x & 31;
    if (warpid >= NN) return;

    const int d   = warpid;
    const int off = g_off[d];
    const int jend = off + g_deg[d];

    const int hl = lane >> 3;
    const float adh = __ldg(g_adst + d * HH + hl);

    float acc[8];
    #pragma unroll
    for (int i = 0; i < 8; i++) acc[i] = 0.f;
    float den = 0.f;

    const uint4* xb = reinterpret_cast<const uint4*>(g_xhh);

    int s = d;  // first iteration = implicit self-loop
    for (int j = off - 1; j < jend; j++) {
        int snext = (j + 1 < jend) ? __ldg(g_eidx + j + 1) : 0;

        float a = __ldg(g_asrc + s * HH + hl) + adh;
        float w = __expf(leaky(a));
        if ((lane & 7) == 0) den += w;

        uint4 v = xb[(size_t)s * 32 + lane];
        const __half2* pv = reinterpret_cast<const __half2*>(&v);
        #pragma unroll
        for (int q = 0; q < 4; q++) {
            float2 f = __half22float2(pv[q]);
            acc[2 * q]     = fmaf(w, f.x, acc[2 * q]);
            acc[2 * q + 1] = fmaf(w, f.y, acc[2 * q + 1]);
        }
        s = snext;
    }

    float r = ((lane & 7) == 0) ? (1.f / den) : 0.f;
    r = __shfl_sync(FULL, r, lane & 24);

    float o[8];
    #pragma unroll
    for (int i = 0; i < 8; i++) {
        float v = acc[i] * r;
        v += __shfl_xor_sync(FULL, v, 8);
        v += __shfl_xor_sync(FULL, v, 16);
        o[i] = v;
    }

    if (lane < 8) {
        int c = lane * 8;
        float4 o0, o1;
        #pragma unroll
        for (int i = 0; i < 8; i++) {
            float b = __ldg(cb + c + i) + __ldg(lb + c + i);
            float v = fmaf(o[i], 0.25f, b);
            v = v > 0.f ? v : 0.f;
            if (i < 4) (&o0.x)[i] = v; else (&o1.x)[i - 4] = v;
        }
        float4* po4 = reinterpret_cast<float4*>(out + (size_t)d * OUTC + c);
        po4[0] = o0;
        po4[1] = o1;
    }
}

// -------- launch: fork CSR-build chain onto a side stream, join before aggregate --------
extern "C" void kernel_launch(void* const* d_in, const int* in_sizes, int n_in,
                              void* d_out, int out_size)
{
    const float* x     = (const float*)d_in[0];
    const int*   ei    = (const int*)  d_in[1];
    const float* w     = (const float*)d_in[2];
    const float* att_s = (const float*)d_in[3];
    const float* att_d = (const float*)d_in[4];
    const float* cb    = (const float*)d_in[5];
    const float* lb    = (const float*)d_in[6];
    float* out = (float*)d_out;

    static cudaStream_t s2 = nullptr;
    static cudaEvent_t evFork = nullptr, evJoin = nullptr;
    if (s2 == nullptr) {
        cudaStreamCreateWithFlags(&s2, cudaStreamNonBlocking);
        cudaEventCreateWithFlags(&evFork, cudaEventDisableTiming);
        cudaEventCreateWithFlags(&evJoin, cudaEventDisableTiming);
    }

    // fork: side stream inherits current position of the main (capturing) stream
    cudaEventRecord(evFork, 0);
    cudaStreamWaitEvent(s2, evFork, 0);

    // CSR-build chain on side stream
    zero_kernel<<<(NN + 255) / 256, 256, 0, s2>>>();
    hist_kernel<<<(EE / 4 + 255) / 256, 256, 0, s2>>>(ei);
    scan1_kernel<<<SCAN_BLOCKS, 1024, 0, s2>>>();
    scan2_kernel<<<1, 32, 0, s2>>>();
    scan3_kernel<<<(NN + 255) / 256, 256, 0, s2>>>();
    scatter_kernel<<<(EE / 4 + 255) / 256, 256, 0, s2>>>(ei);

    // GEMM (+ logits) on main stream, concurrent with CSR build
    gemm_kernel<<<dim3(HC / GBN, (NN + GBM - 1) / GBM), 256>>>(x, w, att_s, att_d);

    // join
    cudaEventRecord(evJoin, s2);
    cudaStreamWaitEvent(0, evJoin, 0);

    aggregate_kernel<<<(NN * 32 + 255) / 256, 256>>>(cb, lb, out);
}